// round 12
// baseline (speedup 1.0000x reference)
#include <cuda_runtime.h>
#include <cstdint>

// Problem constants: B=1024, V=100000, C=1024
#define C_CLUSTERS 1024
#define MAX_B      1024
#define MAX_V      100352
#define NCHUNK     8
#define CH         12500                       // elements per chunk
#define CHP        12800                       // padded: multiple of 512
#define T_PER_THR  (CHP / 512)                 // 25 sorted entries per thread
#define SENT_PACK  ((1024u << 16) | (CHP - 1)) // sentinel: c=1024 -> guarded, slot zeroed

// Scratch (__device__ globals per allocation-free rule)
__device__ float    g_sums[(size_t)MAX_B * C_CLUSTERS];   // exp-sums -> log-denom (in place)
__device__ unsigned g_counts[NCHUNK * C_CLUSTERS];        // hist -> cursors
__device__ unsigned g_sorted[NCHUNK * CHP];               // packed (c<<16)|lpos, sorted by c
__device__ __align__(16) unsigned short g_idx16[MAX_V];   // compact index for pass2
__device__ unsigned g_nzero;                              // # positions with c==0
__device__ unsigned g_zpos[MAX_V];                        // those positions

// ---------------------------------------------------------------------------
// Prep kernels
// ---------------------------------------------------------------------------
__global__ void init_kernel(int nsums, int nsorted, int ncounts) {
    int i0 = blockIdx.x * blockDim.x + threadIdx.x;
    int st = gridDim.x * blockDim.x;
    for (int i = i0; i < nsums;   i += st) g_sums[i]   = 0.0f;
    for (int i = i0; i < nsorted; i += st) g_sorted[i] = SENT_PACK;
    for (int i = i0; i < ncounts; i += st) g_counts[i] = 0u;
    if (i0 == 0) g_nzero = 0u;
}

__global__ void idx_hist_kernel(const int* __restrict__ cidx, int V) {
    int i = blockIdx.x * blockDim.x + threadIdx.x;
    if (i < V) {
        int c = cidx[i];
        g_idx16[i] = (unsigned short)c;
        atomicAdd(&g_counts[(i / CH) * C_CLUSTERS + c], 1u);
        if (c == 0) {
            unsigned k = atomicAdd(&g_nzero, 1u);
            g_zpos[k] = (unsigned)i;
        }
    }
}

__global__ void scan_kernel() {   // per-chunk exclusive scan -> scatter cursors
    __shared__ unsigned s[C_CLUSTERS];
    int t = threadIdx.x;
    for (int ch = 0; ch < NCHUNK; ch++) {
        unsigned x = g_counts[ch * C_CLUSTERS + t];
        s[t] = x; __syncthreads();
        for (int d = 1; d < C_CLUSTERS; d <<= 1) {
            unsigned v = (t >= d) ? s[t - d] : 0u;
            __syncthreads();
            s[t] += v;
            __syncthreads();
        }
        g_counts[ch * C_CLUSTERS + t] = s[t] - x;   // exclusive
        __syncthreads();
    }
}

__global__ void scatter_kernel(const int* __restrict__ cidx, int V) {
    int i = blockIdx.x * blockDim.x + threadIdx.x;
    if (i < V) {
        int ch = i / CH, lpos = i - ch * CH;
        int c = cidx[i];
        unsigned p = atomicAdd(&g_counts[ch * C_CLUSTERS + c], 1u);
        g_sorted[ch * CHP + p] = ((unsigned)c << 16) | (unsigned)lpos;
    }
}

// ---------------------------------------------------------------------------
// Pass 1: segment-sum of exp via sorted sweep (unchanged from R9).
// ---------------------------------------------------------------------------
__global__ void __launch_bounds__(512, 2)
pass1_sweep_kernel(const float* __restrict__ logits, int V) {
    extern __shared__ float smem[];
    float*    s_exp  = smem;                          // CHP floats
    unsigned* s_perm = (unsigned*)(smem + CHP);       // CHP words

    const int ch  = blockIdx.x;
    const int b   = blockIdx.y;
    const int tid = threadIdx.x;
    const int base = ch * CH;
    const int n    = min(CH, V - base);
    const float* src = logits + (size_t)b * V + base;

    const int n4 = n >> 2;
    const float4* src4 = (const float4*)src;
    #pragma unroll 4
    for (int i = tid; i < n4; i += 512) {
        float4 x = __ldcs(&src4[i]);
        float4 e;
        e.x = __expf(x.x); e.y = __expf(x.y);
        e.z = __expf(x.z); e.w = __expf(x.w);
        *(float4*)&s_exp[i * 4] = e;
    }
    for (int i = (n4 << 2) + tid; i < n; i += 512) s_exp[i] = __expf(src[i]);
    for (int i = n + tid; i < CHP; i += 512) s_exp[i] = 0.0f;   // sentinel slots

    const uint4* p4 = (const uint4*)(g_sorted + ch * CHP);
    #pragma unroll 2
    for (int i = tid; i < CHP / 4; i += 512) ((uint4*)s_perm)[i] = p4[i];
    __syncthreads();

    float* srow = g_sums + (size_t)b * C_CLUSTERS;
    const int o = tid * T_PER_THR;
    unsigned e0   = s_perm[o];
    unsigned prev = e0 >> 16;
    float    acc  = s_exp[e0 & 0xffffu];
    #pragma unroll
    for (int j = 1; j < T_PER_THR; j++) {
        unsigned e = s_perm[o + j];
        unsigned c = e >> 16;
        float    v = s_exp[e & 0xffffu];
        if (c != prev) {
            if (prev < C_CLUSTERS) atomicAdd(&srow[prev], acc);
            prev = c; acc = v;
        } else {
            acc += v;
        }
    }
    if (prev < C_CLUSTERS) atomicAdd(&srow[prev], acc);
}

// ---------------------------------------------------------------------------
// Log kernel: sums -> log-denominator, in place (1M logf, ~3us)
// ---------------------------------------------------------------------------
__global__ void log_kernel(int n) {
    int i = blockIdx.x * blockDim.x + threadIdx.x;
    if (i < n) g_sums[i] = logf(fmaxf(g_sums[i], 1e-20f));   // SAFE_LOG_MIN clamp
}

// ---------------------------------------------------------------------------
// Pass 2: BRANCH-FREE stream: out[b][v] = x - logdenom[b][c].
// Cluster-0 positions get a wrong-but-overwritten value; fixup follows.
// ---------------------------------------------------------------------------
#define P2_SPLITS 8
__global__ __launch_bounds__(512)
void pass2_kernel(const float* __restrict__ logits, float* __restrict__ out,
                  int B, int V) {
    __shared__ float s_d[C_CLUSTERS];
    const int b = blockIdx.y;
    const float* drow = g_sums + (size_t)b * C_CLUSTERS;   // already log-ed
    for (int i = threadIdx.x; i < C_CLUSTERS; i += blockDim.x) s_d[i] = drow[i];
    __syncthreads();

    const float* row  = logits + (size_t)b * V;
    float*       orow = out    + (size_t)b * V;

    const int V4 = V >> 2;
    const float4*  row4  = (const float4*)row;
    float4*        orow4 = (float4*)orow;
    const ushort4* idx4  = (const ushort4*)g_idx16;

    const int chunk = (V4 + P2_SPLITS - 1) / P2_SPLITS;
    const int start = blockIdx.x * chunk;
    const int end   = min(start + chunk, V4);

    #pragma unroll 4
    for (int i = start + (int)threadIdx.x; i < end; i += (int)blockDim.x) {
        float4  x = __ldcs(&row4[i]);
        ushort4 c = idx4[i];
        float4 r;
        r.x = x.x - s_d[c.x];
        r.y = x.y - s_d[c.y];
        r.z = x.z - s_d[c.z];
        r.w = x.w - s_d[c.w];
        __stcs(&orow4[i], r);
    }
    if (blockIdx.x == P2_SPLITS - 1) {   // tail (V % 4)
        for (int i = (V4 << 2) + (int)threadIdx.x; i < V; i += (int)blockDim.x) {
            orow[i] = row[i] - s_d[g_idx16[i]];
        }
    }
}

// ---------------------------------------------------------------------------
// Fixup: cluster-0 positions -> log-sigmoid(x) = x - log1p(exp(x))
// ~98 positions x 1024 rows = ~100K scattered elements (~3us)
// ---------------------------------------------------------------------------
__global__ void fixup_kernel(const float* __restrict__ logits,
                             float* __restrict__ out, int V) {
    const int b = blockIdx.x;
    const unsigned nz = g_nzero;
    const float* row  = logits + (size_t)b * V;
    float*       orow = out    + (size_t)b * V;
    for (unsigned j = threadIdx.x; j < nz; j += blockDim.x) {
        unsigned p = g_zpos[j];
        float x = row[p];
        orow[p] = x - log1pf(__expf(x));
    }
}

// ---------------------------------------------------------------------------
extern "C" void kernel_launch(void* const* d_in, const int* in_sizes, int n_in,
                              void* d_out, int out_size) {
    const float* logits = (const float*)d_in[0];
    const int*   cidx   = (const int*)d_in[1];
    const int V = in_sizes[1];
    const int B = in_sizes[0] / V;

    static bool attr_set = false;
    const int SMEM_BYTES = 2 * CHP * 4;   // 102,400 B
    if (!attr_set) {
        cudaFuncSetAttribute(pass1_sweep_kernel,
                             cudaFuncAttributeMaxDynamicSharedMemorySize, SMEM_BYTES);
        attr_set = true;
    }

    // prep
    init_kernel<<<512, 256>>>(MAX_B * C_CLUSTERS, NCHUNK * CHP, NCHUNK * C_CLUSTERS);
    {
        int th = 256, bl = (V + th - 1) / th;
        idx_hist_kernel<<<bl, th>>>(cidx, V);
        scan_kernel<<<1, C_CLUSTERS>>>();
        scatter_kernel<<<bl, th>>>(cidx, V);
    }

    // pass 1: sorted-sweep segment sums
    {
        dim3 grid(NCHUNK, B, 1);
        pass1_sweep_kernel<<<grid, 512, SMEM_BYTES>>>(logits, V);
    }

    // sums -> log-denominator (in place)
    {
        int n = B * C_CLUSTERS;
        log_kernel<<<(n + 255) / 256, 256>>>(n);
    }

    // pass 2: branch-free streaming output
    {
        dim3 grid(P2_SPLITS, B, 1);
        pass2_kernel<<<grid, 512>>>(logits, (float*)d_out, B, V);
    }

    // cluster-0 fixup
    fixup_kernel<<<B, 128>>>(logits, (float*)d_out, V);
}

// round 15
// speedup vs baseline: 1.0597x; 1.0597x over previous
#include <cuda_runtime.h>
#include <cstdint>

// Problem constants: B=1024, V=100000, C=1024
#define C_CLUSTERS 1024
#define MAX_B      1024
#define MAX_V      100352
#define NCHUNK     8
#define CH         12500                       // elements per chunk
#define CHP        12800                       // padded: multiple of 512
#define T_PER_THR  (CHP / 512)                 // 25 sorted entries per thread
#define SENT_PACK  ((1024u << 16) | (CHP - 1)) // sentinel: c=1024 guarded, lpos->zeroed slot
#define PREP_ZERO_BLOCKS 32

// Scratch (__device__ globals per allocation-free rule)
__device__ float    g_sums[(size_t)MAX_B * C_CLUSTERS];   // exp-sums -> log-denom (in place)
__device__ unsigned g_sorted[NCHUNK * CHP];               // packed (c<<16)|lpos, sorted by c
__device__ __align__(16) unsigned short g_idx16[MAX_V];   // compact index for pass2

// ---------------------------------------------------------------------------
// Prep (ONE kernel): per-chunk hist -> exclusive scan -> scatter, all in smem.
// Blocks 0..NCHUNK-1 do chunk work; blocks NCHUNK.. zero g_sums.
// ---------------------------------------------------------------------------
__global__ void __launch_bounds__(512)
prep_kernel(const int* __restrict__ cidx, int V, int B) {
    const int blk = blockIdx.x;
    const int tid = threadIdx.x;

    if (blk >= NCHUNK) {               // zero g_sums (4 MB over 32 blocks)
        const size_t total4 = ((size_t)B * C_CLUSTERS) >> 2;
        const int z = blk - NCHUNK;
        float4* p = (float4*)g_sums;
        for (size_t i = (size_t)z * 512 + tid; i < total4;
             i += (size_t)PREP_ZERO_BLOCKS * 512)
            p[i] = make_float4(0.f, 0.f, 0.f, 0.f);
        return;
    }

    __shared__ unsigned cnt[C_CLUSTERS];
    __shared__ unsigned cur[C_CLUSTERS];
    __shared__ unsigned wtot[16];

    cnt[tid] = 0u; cnt[tid + 512] = 0u;
    __syncthreads();

    const int base = blk * CH;
    const int n    = min(CH, V - base);

    for (int i = tid; i < n; i += 512) {
        int c = cidx[base + i];
        g_idx16[base + i] = (unsigned short)c;
        atomicAdd(&cnt[c], 1u);
    }
    __syncthreads();

    // exclusive scan of 1024 counters with 512 threads (thread t owns 2t,2t+1)
    unsigned a  = cnt[2 * tid], b2 = cnt[2 * tid + 1];
    unsigned ts = a + b2;
    unsigned lane = tid & 31, w = tid >> 5;
    unsigned inc = ts;
    #pragma unroll
    for (int d = 1; d < 32; d <<= 1) {
        unsigned v = __shfl_up_sync(0xffffffffu, inc, d);
        if (lane >= d) inc += v;
    }
    if (lane == 31) wtot[w] = inc;
    __syncthreads();
    if (w == 0) {
        unsigned v = (lane < 16) ? wtot[lane] : 0u;
        #pragma unroll
        for (int d = 1; d < 16; d <<= 1) {
            unsigned t2 = __shfl_up_sync(0xffffffffu, v, d);
            if (lane >= d) v += t2;
        }
        if (lane < 16) wtot[lane] = v;   // inclusive warp totals
    }
    __syncthreads();
    unsigned woff = (w > 0) ? wtot[w - 1] : 0u;
    unsigned excl = woff + inc - ts;
    cur[2 * tid]     = excl;
    cur[2 * tid + 1] = excl + a;
    __syncthreads();

    // scatter own chunk via smem cursors
    for (int i = tid; i < n; i += 512) {
        int c = cidx[base + i];
        unsigned p = atomicAdd(&cur[c], 1u);
        g_sorted[blk * CHP + p] = ((unsigned)c << 16) | (unsigned)i;
    }
    // pad fill (positions n..CHP)
    for (int j = n + tid; j < CHP; j += 512)
        g_sorted[blk * CHP + j] = SENT_PACK;
}

// ---------------------------------------------------------------------------
// Pass 1: segment-sum of exp via sorted sweep (R9-proven form).
// ---------------------------------------------------------------------------
__global__ void __launch_bounds__(512, 2)
pass1_sweep_kernel(const float* __restrict__ logits, int V) {
    extern __shared__ float smem[];
    float*    s_exp  = smem;                          // CHP floats
    unsigned* s_perm = (unsigned*)(smem + CHP);       // CHP words

    const int ch  = blockIdx.x;
    const int b   = blockIdx.y;
    const int tid = threadIdx.x;
    const int base = ch * CH;
    const int n    = min(CH, V - base);
    const float* src = logits + (size_t)b * V + base;

    const int n4 = n >> 2;
    const float4* src4 = (const float4*)src;
    #pragma unroll 4
    for (int i = tid; i < n4; i += 512) {
        float4 x = src4[i];
        float4 e;
        e.x = __expf(x.x); e.y = __expf(x.y);
        e.z = __expf(x.z); e.w = __expf(x.w);
        *(float4*)&s_exp[i * 4] = e;
    }
    for (int i = (n4 << 2) + tid; i < n; i += 512) s_exp[i] = __expf(src[i]);
    for (int i = n + tid; i < CHP; i += 512) s_exp[i] = 0.0f;   // sentinel slots

    const uint4* p4 = (const uint4*)(g_sorted + ch * CHP);
    #pragma unroll 2
    for (int i = tid; i < CHP / 4; i += 512) ((uint4*)s_perm)[i] = p4[i];
    __syncthreads();

    float* srow = g_sums + (size_t)b * C_CLUSTERS;
    const int o = tid * T_PER_THR;
    unsigned e0   = s_perm[o];
    unsigned prev = e0 >> 16;
    float    acc  = s_exp[e0 & 0xffffu];
    #pragma unroll
    for (int j = 1; j < T_PER_THR; j++) {
        unsigned e = s_perm[o + j];
        unsigned c = e >> 16;
        float    v = s_exp[e & 0xffffu];
        if (c != prev) {
            if (prev < C_CLUSTERS) atomicAdd(&srow[prev], acc);
            prev = c; acc = v;
        } else {
            acc += v;
        }
    }
    if (prev < C_CLUSTERS) atomicAdd(&srow[prev], acc);
}

// ---------------------------------------------------------------------------
// sums -> log-denominator in place (1M logf, ~4us)
// ---------------------------------------------------------------------------
__global__ void log_kernel(int n) {
    int i = blockIdx.x * blockDim.x + threadIdx.x;
    if (i < n) g_sums[i] = logf(fmaxf(g_sums[i], 1e-20f));   // SAFE_LOG_MIN clamp
}

// ---------------------------------------------------------------------------
// Pass 2 (R9-proven form): out = x - s_d[c]; cluster-0 -> log-sigmoid,
// warp-branched. Table is pre-logged; block just copies it to smem.
// ---------------------------------------------------------------------------
#define P2_SPLITS 4
__global__ __launch_bounds__(512)
void pass2_kernel(const float* __restrict__ logits, float* __restrict__ out,
                  int B, int V) {
    __shared__ float s_d[C_CLUSTERS];
    const int b = blockIdx.y;
    const float* drow = g_sums + (size_t)b * C_CLUSTERS;   // already log-ed
    for (int i = threadIdx.x; i < C_CLUSTERS; i += blockDim.x) s_d[i] = drow[i];
    __syncthreads();

    const float* row  = logits + (size_t)b * V;
    float*       orow = out    + (size_t)b * V;

    const int V4 = V >> 2;
    const float4*  row4  = (const float4*)row;
    float4*        orow4 = (float4*)orow;
    const ushort4* idx4  = (const ushort4*)g_idx16;

    const int chunk = (V4 + P2_SPLITS - 1) / P2_SPLITS;
    const int start = blockIdx.x * chunk;
    const int end   = min(start + chunk, V4);

    for (int i = start + (int)threadIdx.x; i < end; i += (int)blockDim.x) {
        float4  x = row4[i];
        ushort4 c = idx4[i];
        float4 r;
        r.x = x.x - s_d[c.x];
        r.y = x.y - s_d[c.y];
        r.z = x.z - s_d[c.z];
        r.w = x.w - s_d[c.w];
        bool need = (c.x == 0) | (c.y == 0) | (c.z == 0) | (c.w == 0);
        if (__any_sync(0xffffffffu, need)) {  // rare log-sigmoid path
            if (c.x == 0) r.x = x.x - log1pf(__expf(x.x));
            if (c.y == 0) r.y = x.y - log1pf(__expf(x.y));
            if (c.z == 0) r.z = x.z - log1pf(__expf(x.z));
            if (c.w == 0) r.w = x.w - log1pf(__expf(x.w));
        }
        orow4[i] = r;
    }
    if (blockIdx.x == P2_SPLITS - 1) {   // tail (V % 4)
        for (int i = (V4 << 2) + (int)threadIdx.x; i < V; i += (int)blockDim.x) {
            float x = row[i];
            unsigned short c = g_idx16[i];
            orow[i] = (c == 0) ? (x - log1pf(__expf(x))) : (x - s_d[c]);
        }
    }
}

// ---------------------------------------------------------------------------
extern "C" void kernel_launch(void* const* d_in, const int* in_sizes, int n_in,
                              void* d_out, int out_size) {
    const float* logits = (const float*)d_in[0];
    const int*   cidx   = (const int*)d_in[1];
    const int V = in_sizes[1];
    const int B = in_sizes[0] / V;

    static bool attr_set = false;
    const int SMEM_BYTES = 2 * CHP * 4;   // 102,400 B
    if (!attr_set) {
        cudaFuncSetAttribute(pass1_sweep_kernel,
                             cudaFuncAttributeMaxDynamicSharedMemorySize, SMEM_BYTES);
        attr_set = true;
    }

    // 1) fused prep: per-chunk hist+scan+scatter, plus g_sums zeroing
    prep_kernel<<<NCHUNK + PREP_ZERO_BLOCKS, 512>>>(cidx, V, B);

    // 2) pass 1: sorted-sweep segment sums
    {
        dim3 grid(NCHUNK, B, 1);
        pass1_sweep_kernel<<<grid, 512, SMEM_BYTES>>>(logits, V);
    }

    // 3) sums -> log-denominator (in place)
    {
        int n = B * C_CLUSTERS;
        log_kernel<<<(n + 255) / 256, 256>>>(n);
    }

    // 4) pass 2: streaming output  (overall launch slot #5 -> ncu profiles THIS)
    {
        dim3 grid(P2_SPLITS, B, 1);
        pass2_kernel<<<grid, 512>>>(logits, (float*)d_out, B, V);
    }
}

// round 16
// speedup vs baseline: 1.1309x; 1.0672x over previous
#include <cuda_runtime.h>
#include <cstdint>

// Problem constants: B=1024, V=100000, C=1024
#define C_CLUSTERS 1024
#define MAX_B      1024
#define MAX_V      100352
#define NCHUNK     8
#define CH         12500                       // elements per chunk
#define CHP        12800                       // padded: 512*25
#define T_PER_THR  25
#define ZERO_BLOCKS 32

// Scratch (__device__ globals per allocation-free rule)
__device__ float          g_sums[(size_t)MAX_B * C_CLUSTERS]; // exp-sums -> log-denom
__device__ int            g_cstart[NCHUNK * 1025];            // per-chunk cluster start offsets
__device__ __align__(16) unsigned short g_invp[NCHUNK * CHP]; // orig pos -> sorted pos
__device__ __align__(16) unsigned short g_idx16[MAX_V];       // compact index for pass2

// ---------------------------------------------------------------------------
// Prep: per-chunk hist -> exclusive scan -> start table + inverse permutation
// ---------------------------------------------------------------------------
__global__ void __launch_bounds__(512)
prep_kernel(const int* __restrict__ cidx, int V) {
    const int blk = blockIdx.x;          // chunk id
    const int tid = threadIdx.x;

    __shared__ unsigned cnt[C_CLUSTERS];
    __shared__ unsigned cur[C_CLUSTERS];
    __shared__ unsigned wtot[16];

    cnt[tid] = 0u; cnt[tid + 512] = 0u;
    __syncthreads();

    const int base = blk * CH;
    const int n    = min(CH, V - base);

    for (int i = tid; i < n; i += 512) {
        int c = cidx[base + i];
        g_idx16[base + i] = (unsigned short)c;
        atomicAdd(&cnt[c], 1u);
    }
    __syncthreads();

    // exclusive scan of 1024 counters (thread t owns counters 2t, 2t+1)
    unsigned a  = cnt[2 * tid], b2 = cnt[2 * tid + 1];
    unsigned ts = a + b2;
    unsigned lane = tid & 31, w = tid >> 5;
    unsigned inc = ts;
    #pragma unroll
    for (int d = 1; d < 32; d <<= 1) {
        unsigned v = __shfl_up_sync(0xffffffffu, inc, d);
        if (lane >= d) inc += v;
    }
    if (lane == 31) wtot[w] = inc;
    __syncthreads();
    if (w == 0) {
        unsigned v = (lane < 16) ? wtot[lane] : 0u;
        #pragma unroll
        for (int d = 1; d < 16; d <<= 1) {
            unsigned t2 = __shfl_up_sync(0xffffffffu, v, d);
            if (lane >= d) v += t2;
        }
        if (lane < 16) wtot[lane] = v;
    }
    __syncthreads();
    unsigned woff = (w > 0) ? wtot[w - 1] : 0u;
    unsigned excl = woff + inc - ts;
    cur[2 * tid]     = excl;
    cur[2 * tid + 1] = excl + a;
    // persist start table BEFORE scatter mutates cursors
    g_cstart[blk * 1025 + 2 * tid]     = (int)excl;
    g_cstart[blk * 1025 + 2 * tid + 1] = (int)(excl + a);
    if (tid == 0) g_cstart[blk * 1025 + 1024] = n;
    __syncthreads();

    // inverse permutation: orig pos -> sorted pos (coalesced write)
    for (int i = tid; i < n; i += 512) {
        int c = cidx[base + i];
        unsigned p = atomicAdd(&cur[c], 1u);
        g_invp[blk * CHP + i] = (unsigned short)p;
    }
}

// ---------------------------------------------------------------------------
// Zero g_sums (also serves as launch-slot filler #2)
// ---------------------------------------------------------------------------
__global__ void zero_sums_kernel(int B) {
    const size_t total4 = ((size_t)B * C_CLUSTERS) >> 2;
    float4* p = (float4*)g_sums;
    for (size_t i = (size_t)blockIdx.x * blockDim.x + threadIdx.x; i < total4;
         i += (size_t)gridDim.x * blockDim.x)
        p[i] = make_float4(0.f, 0.f, 0.f, 0.f);
}

// ---------------------------------------------------------------------------
// Noop filler (#3) so pass1 lands in ncu's profiled slot (#4)
// ---------------------------------------------------------------------------
__global__ void noop_kernel() {
    if (blockIdx.x == 65535u) g_cstart[0] = 0;   // never true; prevents elision
}

// ---------------------------------------------------------------------------
// Pass 1 v3: scatter-into-sorted-order, then sequential conflict-free sweep.
//   load: float4 x (coalesced) + ushort4 invp (coalesced) -> exp -> scattered STS
//   sweep: thread t reads sorted positions [t*25, t*25+25) (stride-25 lanes =
//          conflict-free LDS); run boundaries from cluster-start table (ALU only)
// smem 55.3KB -> 3 CTAs/SM.
// ---------------------------------------------------------------------------
__global__ void __launch_bounds__(512, 3)
pass1_sweep_kernel(const float* __restrict__ logits, int V) {
    extern __shared__ float smem[];
    float* s_exp   = smem;                       // CHP floats
    int*   s_start = (int*)(smem + CHP);         // 1025 ints

    const int ch  = blockIdx.x;
    const int b   = blockIdx.y;
    const int tid = threadIdx.x;
    const int base = ch * CH;
    const int n    = min(CH, V - base);
    const float* src = logits + (size_t)b * V + base;

    // start table -> smem
    for (int i = tid; i < 1025; i += 512) s_start[i] = g_cstart[ch * 1025 + i];

    // load + exp + scatter into sorted position
    const int n4 = n >> 2;
    const float4*  src4  = (const float4*)src;
    const ushort4* invp4 = (const ushort4*)(g_invp + ch * CHP);
    #pragma unroll 4
    for (int i = tid; i < n4; i += 512) {
        float4  x  = src4[i];
        ushort4 ip = invp4[i];
        s_exp[ip.x] = __expf(x.x);
        s_exp[ip.y] = __expf(x.y);
        s_exp[ip.z] = __expf(x.z);
        s_exp[ip.w] = __expf(x.w);
    }
    for (int i = (n4 << 2) + tid; i < n; i += 512) {    // tail
        s_exp[g_invp[ch * CHP + i]] = __expf(src[i]);
    }
    __syncthreads();

    // sweep: consecutive sorted positions, boundaries from start table
    const int o = tid * T_PER_THR;
    if (o < n) {
        // binary search: largest c with s_start[c] <= o  (10 exact steps)
        int lo = 0, hi = 1024;
        #pragma unroll
        for (int it = 0; it < 10; it++) {
            int m = (lo + hi) >> 1;
            if (s_start[m] <= o) lo = m; else hi = m;
        }
        int c   = lo;
        int nxt = s_start[c + 1];
        float acc = 0.f;
        float* srow = g_sums + (size_t)b * C_CLUSTERS;
        const int jend = min(T_PER_THR, n - o);
        for (int j = 0; j < jend; j++) {
            int p = o + j;
            float v = s_exp[p];
            while (p >= nxt) {                 // run boundary (rare: ~1 in 12)
                if (acc > 0.f) atomicAdd(&srow[c], acc);
                acc = 0.f; c++; nxt = s_start[c + 1];
            }
            acc += v;
        }
        if (acc > 0.f) atomicAdd(&srow[c], acc);
    }
}

// ---------------------------------------------------------------------------
// sums -> log-denominator in place
// ---------------------------------------------------------------------------
__global__ void log_kernel(int n) {
    int i = blockIdx.x * blockDim.x + threadIdx.x;
    if (i < n) g_sums[i] = logf(fmaxf(g_sums[i], 1e-20f));   // SAFE_LOG_MIN clamp
}

// ---------------------------------------------------------------------------
// Pass 2 (unchanged; measured 130us @ 75.5% DRAM)
// ---------------------------------------------------------------------------
#define P2_SPLITS 4
__global__ __launch_bounds__(512)
void pass2_kernel(const float* __restrict__ logits, float* __restrict__ out,
                  int B, int V) {
    __shared__ float s_d[C_CLUSTERS];
    const int b = blockIdx.y;
    const float* drow = g_sums + (size_t)b * C_CLUSTERS;   // already log-ed
    for (int i = threadIdx.x; i < C_CLUSTERS; i += blockDim.x) s_d[i] = drow[i];
    __syncthreads();

    const float* row  = logits + (size_t)b * V;
    float*       orow = out    + (size_t)b * V;

    const int V4 = V >> 2;
    const float4*  row4  = (const float4*)row;
    float4*        orow4 = (float4*)orow;
    const ushort4* idx4  = (const ushort4*)g_idx16;

    const int chunk = (V4 + P2_SPLITS - 1) / P2_SPLITS;
    const int start = blockIdx.x * chunk;
    const int end   = min(start + chunk, V4);

    for (int i = start + (int)threadIdx.x; i < end; i += (int)blockDim.x) {
        float4  x = row4[i];
        ushort4 c = idx4[i];
        float4 r;
        r.x = x.x - s_d[c.x];
        r.y = x.y - s_d[c.y];
        r.z = x.z - s_d[c.z];
        r.w = x.w - s_d[c.w];
        bool need = (c.x == 0) | (c.y == 0) | (c.z == 0) | (c.w == 0);
        if (__any_sync(0xffffffffu, need)) {  // rare log-sigmoid path
            if (c.x == 0) r.x = x.x - log1pf(__expf(x.x));
            if (c.y == 0) r.y = x.y - log1pf(__expf(x.y));
            if (c.z == 0) r.z = x.z - log1pf(__expf(x.z));
            if (c.w == 0) r.w = x.w - log1pf(__expf(x.w));
        }
        orow4[i] = r;
    }
    if (blockIdx.x == P2_SPLITS - 1) {   // tail (V % 4)
        for (int i = (V4 << 2) + (int)threadIdx.x; i < V; i += (int)blockDim.x) {
            float x = row[i];
            unsigned short c = g_idx16[i];
            orow[i] = (c == 0) ? (x - log1pf(__expf(x))) : (x - s_d[c]);
        }
    }
}

// ---------------------------------------------------------------------------
extern "C" void kernel_launch(void* const* d_in, const int* in_sizes, int n_in,
                              void* d_out, int out_size) {
    const float* logits = (const float*)d_in[0];
    const int*   cidx   = (const int*)d_in[1];
    const int V = in_sizes[1];
    const int B = in_sizes[0] / V;

    static bool attr_set = false;
    const int SMEM_BYTES = CHP * 4 + 1025 * 4;   // 55,300 B
    if (!attr_set) {
        cudaFuncSetAttribute(pass1_sweep_kernel,
                             cudaFuncAttributeMaxDynamicSharedMemorySize, SMEM_BYTES);
        attr_set = true;
    }

    // 1) prep: hist + scan + start table + inverse perm
    prep_kernel<<<NCHUNK, 512>>>(cidx, V);

    // 2) zero accumulators
    zero_sums_kernel<<<ZERO_BLOCKS, 512>>>(B);

    // 3) filler so pass1 sits in ncu's profiled slot (#4)
    noop_kernel<<<1, 32>>>();

    // 4) pass 1: scatter-sorted sweep segment sums
    {
        dim3 grid(NCHUNK, B, 1);
        pass1_sweep_kernel<<<grid, 512, SMEM_BYTES>>>(logits, V);
    }

    // 5) sums -> log-denominator (in place)
    {
        int n = B * C_CLUSTERS;
        log_kernel<<<(n + 255) / 256, 256>>>(n);
    }

    // 6) pass 2: streaming output
    {
        dim3 grid(P2_SPLITS, B, 1);
        pass2_kernel<<<grid, 512>>>(logits, (float*)d_out, B, V);
    }
}